// round 1
// baseline (speedup 1.0000x reference)
#include <cuda_runtime.h>

// Shapes fixed by the dataset
#define NMAX 100000
#define F    128
#define HID  16
#define C    32

// ---------------- scratch (device globals; no runtime allocation) -----------
__device__ __align__(16) float g_dinv_p[NMAX];
__device__ __align__(16) float g_dinv_n[NMAX];
__device__ __align__(16) float g_hs1p[NMAX * HID];
__device__ __align__(16) float g_hs1n[NMAX * HID];
__device__ __align__(16) float g_acc1p[NMAX * HID];
__device__ __align__(16) float g_acc1n[NMAX * HID];
__device__ __align__(16) float g_h1[NMAX * HID];
__device__ __align__(16) float g_hs2p[NMAX * C];
__device__ __align__(16) float g_hs2n[NMAX * C];
__device__ __align__(16) float g_acc2p[NMAX * C];
__device__ __align__(16) float g_acc2n[NMAX * C];

// ---------------- reduction helpers -----------------------------------------
__device__ __forceinline__ void red_add_f32(float* p, float v) {
    asm volatile("red.global.add.f32 [%0], %1;" :: "l"(p), "f"(v) : "memory");
}
__device__ __forceinline__ void red_add_v4(float* p, float4 v) {
    asm volatile("red.global.add.v4.f32 [%0], {%1,%2,%3,%4};"
                 :: "l"(p), "f"(v.x), "f"(v.y), "f"(v.z), "f"(v.w) : "memory");
}

// ---------------- degree / dinv ----------------------------------------------
__global__ void k_initdeg(int n) {
    int i = blockIdx.x * blockDim.x + threadIdx.x;
    if (i < n) { g_dinv_p[i] = 1.0f; g_dinv_n[i] = 1.0f; }  // self-loop
}

__global__ void k_deg(const int* __restrict__ ep, const int* __restrict__ en, int E) {
    int t = blockIdx.x * blockDim.x + threadIdx.x;
    if (t >= E) return;
    int dp = __ldg(ep + E + t);
    red_add_f32(g_dinv_p + dp, 1.0f);
    int dn = __ldg(en + E + t);
    red_add_f32(g_dinv_n + dn, 1.0f);
}

__global__ void k_rsqrt(int n) {
    int i = blockIdx.x * blockDim.x + threadIdx.x;
    if (i < n) {
        g_dinv_p[i] = rsqrtf(g_dinv_p[i]);   // deg >= 1 always (self loops)
        g_dinv_n[i] = rsqrtf(g_dinv_n[i]);
    }
}

// ---------------- layer-1 GEMM: hs = (x @ W) * dinv, acc init -----------------
// Tile: 64 nodes x 32 out-cols (16 pos | 16 neg), K = 128.
__global__ __launch_bounds__(256) void k_gemm1(
    const float* __restrict__ x,
    const float* __restrict__ W1p, const float* __restrict__ W1n, int n)
{
    __shared__ float Ws[F * 32];          // [k][col], col 0..15 pos, 16..31 neg
    __shared__ float4 Xs4[64 * 32];       // 64 rows x 128 floats as float4
    int tid = threadIdx.x;

    for (int q = tid; q < F * 32; q += 256) {
        int k = q >> 5, c = q & 31;
        Ws[q] = (c < 16) ? W1p[k * 16 + c] : W1n[k * 16 + (c - 16)];
    }
    int node0 = blockIdx.x * 64;
    const float4* x4 = (const float4*)x;
    for (int q = tid; q < 64 * 32; q += 256) {
        int row = q >> 5;
        int node = node0 + row;
        Xs4[q] = (node < n) ? x4[(size_t)node * 32 + (q & 31)]
                            : make_float4(0.f, 0.f, 0.f, 0.f);
    }
    __syncthreads();

    int c  = tid & 31;      // out column
    int rg = tid >> 5;      // warp id -> owns rows r0..r0+7 (broadcast-friendly)
    int r0 = rg * 8;
    float acc[8] = {0.f, 0.f, 0.f, 0.f, 0.f, 0.f, 0.f, 0.f};

    for (int k4 = 0; k4 < 32; k4++) {
        float w0 = Ws[(k4 * 4 + 0) * 32 + c];
        float w1 = Ws[(k4 * 4 + 1) * 32 + c];
        float w2 = Ws[(k4 * 4 + 2) * 32 + c];
        float w3 = Ws[(k4 * 4 + 3) * 32 + c];
        #pragma unroll
        for (int u = 0; u < 8; u++) {
            float4 xv = Xs4[(r0 + u) * 32 + k4];   // broadcast within warp
            acc[u] = fmaf(xv.x, w0, acc[u]);
            acc[u] = fmaf(xv.y, w1, acc[u]);
            acc[u] = fmaf(xv.z, w2, acc[u]);
            acc[u] = fmaf(xv.w, w3, acc[u]);
        }
    }
    #pragma unroll
    for (int u = 0; u < 8; u++) {
        int node = node0 + r0 + u;
        if (node < n) {
            if (c < 16) {
                float s = acc[u] * g_dinv_p[node];
                g_hs1p[node * 16 + c]  = s;
                g_acc1p[node * 16 + c] = s;     // self-loop term
            } else {
                float s = acc[u] * g_dinv_n[node];
                g_hs1n[node * 16 + (c - 16)]  = s;
                g_acc1n[node * 16 + (c - 16)] = s;
            }
        }
    }
}

// ---------------- layer-1 edge aggregation (scatter-add, F=16) ---------------
__global__ void k_agg1(const int* __restrict__ ep, const int* __restrict__ en, int E) {
    int t = blockIdx.x * blockDim.x + threadIdx.x;
    if (t >= E) return;
    {
        int s = __ldg(ep + t), d = __ldg(ep + E + t);
        const float4* src = (const float4*)(g_hs1p + (size_t)s * 16);
        float* dst = g_acc1p + (size_t)d * 16;
        #pragma unroll
        for (int u = 0; u < 4; u++) red_add_v4(dst + u * 4, __ldg(src + u));
    }
    {
        int s = __ldg(en + t), d = __ldg(en + E + t);
        const float4* src = (const float4*)(g_hs1n + (size_t)s * 16);
        float* dst = g_acc1n + (size_t)d * 16;
        #pragma unroll
        for (int u = 0; u < 4; u++) red_add_v4(dst + u * 4, __ldg(src + u));
    }
}

// ---------------- layer-1 epilogue: h1 = relu(pos) - relu(neg) ---------------
__global__ void k_combine1(const float* __restrict__ b1p,
                           const float* __restrict__ b1n, int n) {
    int t = blockIdx.x * blockDim.x + threadIdx.x;
    if (t >= n * HID) return;
    int i = t >> 4, j = t & 15;
    float vp = g_acc1p[t] * g_dinv_p[i] + __ldg(b1p + j);
    float vn = g_acc1n[t] * g_dinv_n[i] + __ldg(b1n + j);
    g_h1[t] = fmaxf(vp, 0.f) - fmaxf(vn, 0.f);
}

// ---------------- layer-2 GEMM: warp per node, grid-stride -------------------
__global__ __launch_bounds__(256) void k_gemm2(
    const float* __restrict__ W2p, const float* __restrict__ W2n, int n)
{
    int c = threadIdx.x & 31;
    float wp[16], wn[16];
    #pragma unroll
    for (int k = 0; k < 16; k++) {
        wp[k] = __ldg(W2p + k * 32 + c);
        wn[k] = __ldg(W2n + k * 32 + c);
    }
    int warp   = (blockIdx.x * blockDim.x + threadIdx.x) >> 5;
    int nwarps = (gridDim.x * blockDim.x) >> 5;
    for (int i = warp; i < n; i += nwarps) {
        float hv = (c < 16) ? g_h1[(size_t)i * 16 + c] : 0.f;
        float ap = 0.f, an = 0.f;
        #pragma unroll
        for (int k = 0; k < 16; k++) {
            float h = __shfl_sync(0xffffffffu, hv, k);
            ap = fmaf(h, wp[k], ap);
            an = fmaf(h, wn[k], an);
        }
        float sp = ap * g_dinv_p[i];
        float sn = an * g_dinv_n[i];
        g_hs2p[(size_t)i * 32 + c]  = sp;
        g_acc2p[(size_t)i * 32 + c] = sp;   // self-loop term
        g_hs2n[(size_t)i * 32 + c]  = sn;
        g_acc2n[(size_t)i * 32 + c] = sn;
    }
}

// ---------------- layer-2 edge aggregation (F=32) ----------------------------
__global__ void k_agg2(const int* __restrict__ ep, const int* __restrict__ en, int E) {
    int t = blockIdx.x * blockDim.x + threadIdx.x;
    if (t >= E) return;
    {
        int s = __ldg(ep + t), d = __ldg(ep + E + t);
        const float4* src = (const float4*)(g_hs2p + (size_t)s * 32);
        float* dst = g_acc2p + (size_t)d * 32;
        #pragma unroll
        for (int u = 0; u < 8; u++) red_add_v4(dst + u * 4, __ldg(src + u));
    }
    {
        int s = __ldg(en + t), d = __ldg(en + E + t);
        const float4* src = (const float4*)(g_hs2n + (size_t)s * 32);
        float* dst = g_acc2n + (size_t)d * 32;
        #pragma unroll
        for (int u = 0; u < 8; u++) red_add_v4(dst + u * 4, __ldg(src + u));
    }
}

// ---------------- final: relu-diff + log_softmax (warp per node) -------------
__global__ void k_softmax(const float* __restrict__ b2p,
                          const float* __restrict__ b2n,
                          float* __restrict__ out, int n) {
    int w = (blockIdx.x * blockDim.x + threadIdx.x) >> 5;
    int c = threadIdx.x & 31;
    if (w >= n) return;
    float vp = g_acc2p[(size_t)w * 32 + c] * g_dinv_p[w] + __ldg(b2p + c);
    float vn = g_acc2n[(size_t)w * 32 + c] * g_dinv_n[w] + __ldg(b2n + c);
    float z  = fmaxf(vp, 0.f) - fmaxf(vn, 0.f);
    float m  = z;
    #pragma unroll
    for (int o = 16; o; o >>= 1) m = fmaxf(m, __shfl_xor_sync(0xffffffffu, m, o));
    float e = __expf(z - m);
    float s = e;
    #pragma unroll
    for (int o = 16; o; o >>= 1) s += __shfl_xor_sync(0xffffffffu, s, o);
    out[(size_t)w * 32 + c] = z - m - __logf(s);
}

// ---------------- launcher ---------------------------------------------------
extern "C" void kernel_launch(void* const* d_in, const int* in_sizes, int n_in,
                              void* d_out, int out_size) {
    const float* x   = (const float*)d_in[0];
    const int*   ep  = (const int*)d_in[1];
    const int*   en  = (const int*)d_in[2];
    const float* W1p = (const float*)d_in[3];
    const float* b1p = (const float*)d_in[4];
    const float* W1n = (const float*)d_in[5];
    const float* b1n = (const float*)d_in[6];
    const float* W2p = (const float*)d_in[7];
    const float* b2p = (const float*)d_in[8];
    const float* W2n = (const float*)d_in[9];
    const float* b2n = (const float*)d_in[10];

    int n = in_sizes[0] / F;          // 100000
    int E = in_sizes[1] / 2;          // 3.2M

    float* out = (float*)d_out;

    k_initdeg <<<(n + 255) / 256, 256>>>(n);
    k_deg     <<<(E + 255) / 256, 256>>>(ep, en, E);
    k_rsqrt   <<<(n + 255) / 256, 256>>>(n);
    k_gemm1   <<<(n + 63) / 64, 256>>>(x, W1p, W1n, n);
    k_agg1    <<<(E + 255) / 256, 256>>>(ep, en, E);
    k_combine1<<<(n * HID + 255) / 256, 256>>>(b1p, b1n, n);
    k_gemm2   <<<2368, 256>>>(W2p, W2n, n);
    k_agg2    <<<(E + 255) / 256, 256>>>(ep, en, E);
    k_softmax <<<(n + 7) / 8, 256>>>(b2p, b2n, out, n);
}

// round 2
// speedup vs baseline: 1.9837x; 1.9837x over previous
#include <cuda_runtime.h>

#define NMAX 100000
#define EMAX 3200000
#define F    128
#define HID  16
#define C    32

// ---------------- scratch (device globals; no runtime allocation) -----------
__device__ __align__(16) int   g_cnt[2 * NMAX];
__device__ __align__(16) int   g_off[2 * NMAX];
__device__ __align__(16) int   g_cur[2 * NMAX];
__device__ __align__(16) float g_dinv[2 * NMAX];
__device__ __align__(16) int   g_bsum[256];
__device__ __align__(16) int   g_adj[2 * EMAX];
__device__ __align__(16) float g_hs1p[NMAX * HID];
__device__ __align__(16) float g_hs1n[NMAX * HID];
__device__ __align__(16) float g_hs2p[NMAX * C];
__device__ __align__(16) float g_hs2n[NMAX * C];

// ---------------- float4 helpers ---------------------------------------------
__device__ __forceinline__ void f4acc(float4& a, float4 b) {
    a.x += b.x; a.y += b.y; a.z += b.z; a.w += b.w;
}
__device__ __forceinline__ float4 f4shflx(float4 v, int m) {
    float4 r;
    r.x = __shfl_xor_sync(0xffffffffu, v.x, m);
    r.y = __shfl_xor_sync(0xffffffffu, v.y, m);
    r.z = __shfl_xor_sync(0xffffffffu, v.z, m);
    r.w = __shfl_xor_sync(0xffffffffu, v.w, m);
    return r;
}

// ---------------- CSR build ---------------------------------------------------
__global__ void k_zero(int m) {
    int i = blockIdx.x * blockDim.x + threadIdx.x;
    if (i < m) g_cnt[i] = 0;
}

__global__ void k_hist(const int* __restrict__ ep, const int* __restrict__ en,
                       int E, int n) {
    int t = blockIdx.x * blockDim.x + threadIdx.x;
    if (t >= E) return;
    atomicAdd(g_cnt + __ldg(ep + E + t), 1);
    atomicAdd(g_cnt + n + __ldg(en + E + t), 1);
}

// exclusive scan over g_cnt[0..2n), 1024-wide blocks
__global__ __launch_bounds__(1024) void k_scan1(int twoN) {
    __shared__ int sh[1024];
    int t = threadIdx.x;
    int g = blockIdx.x * 1024 + t;
    int v = (g < twoN) ? g_cnt[g] : 0;
    sh[t] = v;
    __syncthreads();
    #pragma unroll
    for (int o = 1; o < 1024; o <<= 1) {
        int add = (t >= o) ? sh[t - o] : 0;
        __syncthreads();
        sh[t] += add;
        __syncthreads();
    }
    if (g < twoN) g_off[g] = sh[t] - v;     // exclusive within block
    if (t == 1023) g_bsum[blockIdx.x] = sh[t];
}

__global__ __launch_bounds__(256) void k_scan2(int nb) {
    __shared__ int sh[256];
    int t = threadIdx.x;
    int v = (t < nb) ? g_bsum[t] : 0;
    sh[t] = v;
    __syncthreads();
    #pragma unroll
    for (int o = 1; o < 256; o <<= 1) {
        int add = (t >= o) ? sh[t - o] : 0;
        __syncthreads();
        sh[t] += add;
        __syncthreads();
    }
    if (t < nb) g_bsum[t] = sh[t] - v;      // exclusive
}

__global__ void k_scan3(int twoN) {
    int g = blockIdx.x * blockDim.x + threadIdx.x;
    if (g >= twoN) return;
    int o = g_off[g] + g_bsum[g >> 10];
    g_off[g] = o;
    g_cur[g] = o;
    g_dinv[g] = rsqrtf(1.0f + (float)g_cnt[g]);   // self-loop => deg+1
}

__global__ void k_fill(const int* __restrict__ ep, const int* __restrict__ en,
                       int E, int n) {
    int t = blockIdx.x * blockDim.x + threadIdx.x;
    if (t >= E) return;
    {
        int s = __ldg(ep + t), d = __ldg(ep + E + t);
        int p = atomicAdd(g_cur + d, 1);
        g_adj[p] = s;
    }
    {
        int s = __ldg(en + t), d = __ldg(en + E + t);
        int p = atomicAdd(g_cur + n + d, 1);
        g_adj[p] = s;
    }
}

// ---------------- layer-1 GEMM: hs = (x @ W) * dinv ---------------------------
__global__ __launch_bounds__(256) void k_gemm1(
    const float* __restrict__ x,
    const float* __restrict__ W1p, const float* __restrict__ W1n, int n)
{
    __shared__ float Ws[F * 32];
    __shared__ float4 Xs4[64 * 32];
    int tid = threadIdx.x;

    for (int q = tid; q < F * 32; q += 256) {
        int k = q >> 5, c = q & 31;
        Ws[q] = (c < 16) ? W1p[k * 16 + c] : W1n[k * 16 + (c - 16)];
    }
    int node0 = blockIdx.x * 64;
    const float4* x4 = (const float4*)x;
    for (int q = tid; q < 64 * 32; q += 256) {
        int row = q >> 5;
        int node = node0 + row;
        Xs4[q] = (node < n) ? x4[(size_t)node * 32 + (q & 31)]
                            : make_float4(0.f, 0.f, 0.f, 0.f);
    }
    __syncthreads();

    int c  = tid & 31;
    int r0 = (tid >> 5) * 8;
    float acc[8] = {0.f, 0.f, 0.f, 0.f, 0.f, 0.f, 0.f, 0.f};

    for (int k4 = 0; k4 < 32; k4++) {
        float w0 = Ws[(k4 * 4 + 0) * 32 + c];
        float w1 = Ws[(k4 * 4 + 1) * 32 + c];
        float w2 = Ws[(k4 * 4 + 2) * 32 + c];
        float w3 = Ws[(k4 * 4 + 3) * 32 + c];
        #pragma unroll
        for (int u = 0; u < 8; u++) {
            float4 xv = Xs4[(r0 + u) * 32 + k4];
            acc[u] = fmaf(xv.x, w0, acc[u]);
            acc[u] = fmaf(xv.y, w1, acc[u]);
            acc[u] = fmaf(xv.z, w2, acc[u]);
            acc[u] = fmaf(xv.w, w3, acc[u]);
        }
    }
    #pragma unroll
    for (int u = 0; u < 8; u++) {
        int node = node0 + r0 + u;
        if (node < n) {
            if (c < 16)
                g_hs1p[node * 16 + c] = acc[u] * g_dinv[node];
            else
                g_hs1n[node * 16 + (c - 16)] = acc[u] * g_dinv[n + node];
        }
    }
}

// ---------------- gather primitives ------------------------------------------
// 64B rows (4 float4): 8 lane-groups of 4, 8 edges per LDG, 2x unroll
__device__ __forceinline__ float4 gather16(const float4* __restrict__ tab,
                                           int st, int en, int g8, int q) {
    float4 a = make_float4(0.f, 0.f, 0.f, 0.f);
    float4 b = make_float4(0.f, 0.f, 0.f, 0.f);
    int j = st;
    for (; j + 16 <= en; j += 16) {
        int s0 = __ldg(g_adj + j + g8);
        int s1 = __ldg(g_adj + j + 8 + g8);
        f4acc(a, __ldg(tab + (size_t)s0 * 4 + q));
        f4acc(b, __ldg(tab + (size_t)s1 * 4 + q));
    }
    for (; j < en; j += 8) {
        if (j + g8 < en) {
            int s = __ldg(g_adj + j + g8);
            f4acc(a, __ldg(tab + (size_t)s * 4 + q));
        }
    }
    f4acc(a, b);
    return a;
}

// 128B rows (8 float4): 4 lane-groups of 8, 4 edges per LDG, 2x unroll
__device__ __forceinline__ float4 gather32(const float4* __restrict__ tab,
                                           int st, int en, int g4, int q8) {
    float4 a = make_float4(0.f, 0.f, 0.f, 0.f);
    float4 b = make_float4(0.f, 0.f, 0.f, 0.f);
    int j = st;
    for (; j + 8 <= en; j += 8) {
        int s0 = __ldg(g_adj + j + g4);
        int s1 = __ldg(g_adj + j + 4 + g4);
        f4acc(a, __ldg(tab + (size_t)s0 * 8 + q8));
        f4acc(b, __ldg(tab + (size_t)s1 * 8 + q8));
    }
    for (; j < en; j += 4) {
        if (j + g4 < en) {
            int s = __ldg(g_adj + j + g4);
            f4acc(a, __ldg(tab + (size_t)s * 8 + q8));
        }
    }
    f4acc(a, b);
    return a;
}

// ---------------- layer-1 gather + combine + layer-2 GEMM (fused) ------------
__global__ __launch_bounds__(256) void k_agg1g(
    const float* __restrict__ b1p, const float* __restrict__ b1n,
    const float* __restrict__ W2p, const float* __restrict__ W2n, int n)
{
    int lane = threadIdx.x & 31;
    int warp = (blockIdx.x * blockDim.x + threadIdx.x) >> 5;
    int nw   = (gridDim.x * blockDim.x) >> 5;

    float wp[16], wn[16];
    #pragma unroll
    for (int k = 0; k < 16; k++) {
        wp[k] = __ldg(W2p + k * 32 + lane);
        wn[k] = __ldg(W2n + k * 32 + lane);
    }
    int g8 = lane >> 2, q = lane & 3;
    float4 bP = __ldg((const float4*)b1p + q);
    float4 bN = __ldg((const float4*)b1n + q);
    const float4* h1p4 = (const float4*)g_hs1p;
    const float4* h1n4 = (const float4*)g_hs1n;

    for (int i = warp; i < n; i += nw) {
        float dP = g_dinv[i], dN = g_dinv[n + i];

        float4 aP = gather16(h1p4, g_off[i], g_cur[i], g8, q);
        f4acc(aP, f4shflx(aP, 4));
        f4acc(aP, f4shflx(aP, 8));
        f4acc(aP, f4shflx(aP, 16));
        f4acc(aP, __ldg(h1p4 + (size_t)i * 4 + q));        // self loop

        float4 aN = gather16(h1n4, g_off[n + i], g_cur[n + i], g8, q);
        f4acc(aN, f4shflx(aN, 4));
        f4acc(aN, f4shflx(aN, 8));
        f4acc(aN, f4shflx(aN, 16));
        f4acc(aN, __ldg(h1n4 + (size_t)i * 4 + q));

        float4 h4;
        h4.x = fmaxf(aP.x * dP + bP.x, 0.f) - fmaxf(aN.x * dN + bN.x, 0.f);
        h4.y = fmaxf(aP.y * dP + bP.y, 0.f) - fmaxf(aN.y * dN + bN.y, 0.f);
        h4.z = fmaxf(aP.z * dP + bP.z, 0.f) - fmaxf(aN.z * dN + bN.z, 0.f);
        h4.w = fmaxf(aP.w * dP + bP.w, 0.f) - fmaxf(aN.w * dN + bN.w, 0.f);

        // layer-2 GEMM via shuffles: lane = output col
        float ap = 0.f, an = 0.f;
        #pragma unroll
        for (int qq = 0; qq < 4; qq++) {
            float h0 = __shfl_sync(0xffffffffu, h4.x, qq);
            float h1 = __shfl_sync(0xffffffffu, h4.y, qq);
            float h2 = __shfl_sync(0xffffffffu, h4.z, qq);
            float h3 = __shfl_sync(0xffffffffu, h4.w, qq);
            ap = fmaf(h0, wp[qq * 4 + 0], ap);
            ap = fmaf(h1, wp[qq * 4 + 1], ap);
            ap = fmaf(h2, wp[qq * 4 + 2], ap);
            ap = fmaf(h3, wp[qq * 4 + 3], ap);
            an = fmaf(h0, wn[qq * 4 + 0], an);
            an = fmaf(h1, wn[qq * 4 + 1], an);
            an = fmaf(h2, wn[qq * 4 + 2], an);
            an = fmaf(h3, wn[qq * 4 + 3], an);
        }
        g_hs2p[(size_t)i * 32 + lane] = ap * dP;
        g_hs2n[(size_t)i * 32 + lane] = an * dN;
    }
}

// ---------------- layer-2 gather + combine + log_softmax (fused) -------------
__global__ __launch_bounds__(256) void k_agg2g(
    const float* __restrict__ b2p, const float* __restrict__ b2n,
    float* __restrict__ out, int n)
{
    int lane = threadIdx.x & 31;
    int i = (blockIdx.x * blockDim.x + threadIdx.x) >> 5;
    if (i >= n) return;
    int g4 = lane >> 3, q8 = lane & 7;

    const float4* t2p = (const float4*)g_hs2p;
    const float4* t2n = (const float4*)g_hs2n;
    float dP = g_dinv[i], dN = g_dinv[n + i];

    float4 aP = gather32(t2p, g_off[i], g_cur[i], g4, q8);
    f4acc(aP, f4shflx(aP, 8));
    f4acc(aP, f4shflx(aP, 16));
    f4acc(aP, __ldg(t2p + (size_t)i * 8 + q8));            // self loop

    float4 aN = gather32(t2n, g_off[n + i], g_cur[n + i], g4, q8);
    f4acc(aN, f4shflx(aN, 8));
    f4acc(aN, f4shflx(aN, 16));
    f4acc(aN, __ldg(t2n + (size_t)i * 8 + q8));

    float4 bP = __ldg((const float4*)b2p + q8);
    float4 bN = __ldg((const float4*)b2n + q8);

    float4 z;
    z.x = fmaxf(aP.x * dP + bP.x, 0.f) - fmaxf(aN.x * dN + bN.x, 0.f);
    z.y = fmaxf(aP.y * dP + bP.y, 0.f) - fmaxf(aN.y * dN + bN.y, 0.f);
    z.z = fmaxf(aP.z * dP + bP.z, 0.f) - fmaxf(aN.z * dN + bN.z, 0.f);
    z.w = fmaxf(aP.w * dP + bP.w, 0.f) - fmaxf(aN.w * dN + bN.w, 0.f);

    float m = fmaxf(fmaxf(z.x, z.y), fmaxf(z.z, z.w));
    #pragma unroll
    for (int o = 1; o <= 4; o <<= 1) m = fmaxf(m, __shfl_xor_sync(0xffffffffu, m, o));
    float s = __expf(z.x - m) + __expf(z.y - m) + __expf(z.z - m) + __expf(z.w - m);
    #pragma unroll
    for (int o = 1; o <= 4; o <<= 1) s += __shfl_xor_sync(0xffffffffu, s, o);
    float ls = m + __logf(s);

    if (lane < 8) {
        float4 o;
        o.x = z.x - ls; o.y = z.y - ls; o.z = z.z - ls; o.w = z.w - ls;
        ((float4*)out)[(size_t)i * 8 + q8] = o;
    }
}

// ---------------- launcher ----------------------------------------------------
extern "C" void kernel_launch(void* const* d_in, const int* in_sizes, int n_in,
                              void* d_out, int out_size) {
    const float* x   = (const float*)d_in[0];
    const int*   ep  = (const int*)d_in[1];
    const int*   en  = (const int*)d_in[2];
    const float* W1p = (const float*)d_in[3];
    const float* b1p = (const float*)d_in[4];
    const float* W1n = (const float*)d_in[5];
    const float* b1n = (const float*)d_in[6];
    const float* W2p = (const float*)d_in[7];
    const float* b2p = (const float*)d_in[8];
    const float* W2n = (const float*)d_in[9];
    const float* b2n = (const float*)d_in[10];

    int n = in_sizes[0] / F;          // 100000
    int E = in_sizes[1] / 2;          // 3.2M
    int twoN = 2 * n;
    int nScanBlk = (twoN + 1023) / 1024;

    float* out = (float*)d_out;

    k_zero  <<<(twoN + 255) / 256, 256>>>(twoN);
    k_hist  <<<(E + 255) / 256, 256>>>(ep, en, E, n);
    k_scan1 <<<nScanBlk, 1024>>>(twoN);
    k_scan2 <<<1, 256>>>(nScanBlk);
    k_scan3 <<<(twoN + 255) / 256, 256>>>(twoN);
    k_fill  <<<(E + 255) / 256, 256>>>(ep, en, E, n);
    k_gemm1 <<<(n + 63) / 64, 256>>>(x, W1p, W1n, n);
    k_agg1g <<<1600, 256>>>(b1p, b1n, W2p, W2n, n);
    k_agg2g <<<(n + 7) / 8, 256>>>(b2p, b2n, out, n);
}